// round 5
// baseline (speedup 1.0000x reference)
#include <cuda_runtime.h>
#include <cuda_bf16.h>

// DistMult scoring: out[b] = sum_d src[b,d] * M[rel_idx, d] * dst[b,d]
// B = 500000, D = 128. HBM-bound stream (~514 MB traffic).
//
// Layout: 8 lanes per row, 4 rows per warp.
//   lane = 8*sub + sl; row = warp*4 + sub.
//   Each lane loads float4 chunks sl, sl+8, sl+16, sl+24 of src/dst for its row
//   (each load instruction: 8 lanes cover one contiguous 128B chunk per row,
//    4 rows per warp -> 4 x 128B lines, fully coalesced).
//   All 8 src+dst loads are front-batched => MLP 8 per thread.
//   M chunks are identical for all rows -> L1/L2 hits.
//   3-step shuffle reduce within the 8-lane group; sl==0 stores.

__global__ __launch_bounds__(256) void distmult_kernel(
    const float4* __restrict__ src4,
    const float4* __restrict__ dst4,
    const float4* __restrict__ M4,
    const int* __restrict__ rel_idx,
    float* __restrict__ out,
    int B)
{
    const int gtid = blockIdx.x * blockDim.x + threadIdx.x;
    const int warp = gtid >> 5;
    const int lane = threadIdx.x & 31;
    const int sub  = lane >> 3;          // which of the 4 rows this lane serves
    const int sl   = lane & 7;           // sub-lane within the row group

    const long row = (long)warp * 4 + sub;
    if (row >= B) return;

    const int r = __ldg(rel_idx);

    const float4* sp = src4 + row * 32 + sl;
    const float4* dp = dst4 + row * 32 + sl;
    const float4* mp = M4 + (long)r * 32 + sl;

    float4 s[4], d[4], m[4];
    #pragma unroll
    for (int i = 0; i < 4; i++) s[i] = __ldcs(sp + i * 8);   // streaming: read-once
    #pragma unroll
    for (int i = 0; i < 4; i++) d[i] = __ldcs(dp + i * 8);
    #pragma unroll
    for (int i = 0; i < 4; i++) m[i] = __ldg(mp + i * 8);    // hot in L1/L2

    float p0 = 0.f, p1 = 0.f;
    #pragma unroll
    for (int i = 0; i < 4; i++) {
        p0 = fmaf(s[i].x * m[i].x, d[i].x, p0);
        p1 = fmaf(s[i].y * m[i].y, d[i].y, p1);
        p0 = fmaf(s[i].z * m[i].z, d[i].z, p0);
        p1 = fmaf(s[i].w * m[i].w, d[i].w, p1);
    }
    float p = p0 + p1;

    // reduce across the 8-lane group (xor pattern stays within the group)
    p += __shfl_xor_sync(0xffffffffu, p, 4);
    p += __shfl_xor_sync(0xffffffffu, p, 2);
    p += __shfl_xor_sync(0xffffffffu, p, 1);

    if (sl == 0) out[row] = p;   // lanes 0,8,16,24 -> one coalesced 16B segment
}

extern "C" void kernel_launch(void* const* d_in, const int* in_sizes, int n_in,
                              void* d_out, int out_size)
{
    // metadata order: src_emb [B,128] f32, dst_emb [B,128] f32, M [1000,128] f32, rel_idx int32
    const float4* src4 = (const float4*)d_in[0];
    const float4* dst4 = (const float4*)d_in[1];
    const float4* M4   = (const float4*)d_in[2];
    const int* rel_idx = (const int*)d_in[3];
    float* out = (float*)d_out;

    const int B = in_sizes[0] / 128;               // 500000
    const int rows_per_block = (256 / 32) * 4;     // 8 warps * 4 rows = 32 rows
    const int blocks = (B + rows_per_block - 1) / rows_per_block;

    distmult_kernel<<<blocks, 256>>>(src4, dst4, M4, rel_idx, out, B);
}